// round 4
// baseline (speedup 1.0000x reference)
#include <cuda_runtime.h>
#include <cuda_bf16.h>
#include <cstdint>
#include <cstddef>

// Problem constants
#define NB  4
#define NN  4096
#define DD  512
#define NCOL (NB*NN)
#define SEG 16
#define SEGLEN 256
#define CAP 32
#define MAXN (SEG*CAP)

// GEMM tiling: 128x128 CTA tile, 64-wide K chunks, all four split operands
// (A hi/lo, W hi/lo) staged together; 3 passes per chunk; double buffered.
#define BM 128
#define BN 128
#define BK 64
#define NKC 8
#define STG_AH 0
#define STG_AL 16384
#define STG_WH 32768
#define STG_WL 49152
#define STAGE_BYTES 65536
#define GEMM_SMEM (2*STAGE_BYTES)    // 131072

__device__ __forceinline__ uint32_t smem_u32(const void* p) {
    uint32_t a;
    asm("{ .reg .u64 t; cvta.to.shared.u64 t, %1; cvt.u32.u64 %0, t; }" : "=r"(a) : "l"(p));
    return a;
}

#define CPASYNC16(s, g) \
    asm volatile("cp.async.cg.shared.global [%0], [%1], 16;" :: "r"(s), "l"(g) : "memory")
#define CP_COMMIT() asm volatile("cp.async.commit_group;" ::: "memory")

#define LDMX4(d, a) \
    asm volatile("ldmatrix.sync.aligned.m8n8.x4.shared.b16 {%0,%1,%2,%3}, [%4];" \
        : "=r"((d)[0]), "=r"((d)[1]), "=r"((d)[2]), "=r"((d)[3]) : "r"(a))

#define MMA16816(c, a, b) \
    asm volatile("mma.sync.aligned.m16n8k16.row.col.f32.bf16.bf16.f32 " \
        "{%0,%1,%2,%3},{%4,%5,%6,%7},{%8,%9},{%0,%1,%2,%3};" \
        : "+f"((c)[0]), "+f"((c)[1]), "+f"((c)[2]), "+f"((c)[3]) \
        : "r"((a)[0]), "r"((a)[1]), "r"((a)[2]), "r"((a)[3]), "r"((b)[0]), "r"((b)[1]))

// ---------------------------------------------------------------------------
// Static scratch
// ---------------------------------------------------------------------------
__device__ int   g_scnt[NCOL*SEG];
__device__ int   g_sidx[(size_t)NCOL*SEG*CAP];
__device__ float g_dvec[NCOL];
__device__ float g_buf0[(size_t)NCOL*DD];          // GEMM output Z (fp32)
__device__ __nv_bfloat16 g_hi[(size_t)NCOL*DD];    // activation hi
__device__ __nv_bfloat16 g_lo[(size_t)NCOL*DD];    // activation lo
__device__ __nv_bfloat16 g_wh[3][(size_t)DD*DD];   // W^T hi
__device__ __nv_bfloat16 g_wl[3][(size_t)DD*DD];   // W^T lo

// ---------------------------------------------------------------------------
// Adjacency sparsify + degrees
// ---------------------------------------------------------------------------
__global__ __launch_bounds__(256) void build_kernel(const float* __restrict__ adj)
{
    int colg = blockIdx.x * 256 + threadIdx.x;
    int s    = blockIdx.y;
    int b    = colg >> 12;
    int i    = colg & (NN - 1);

    const float* base = adj + (size_t)b * NN * NN + i;
    int j0  = s * SEGLEN;
    int cnt = 0;
    int out = (colg * SEG + s) * CAP;

    #pragma unroll 4
    for (int jj = 0; jj < SEGLEN; jj++) {
        float v = __ldg(base + (size_t)(j0 + jj) * NN);
        if (v != 0.0f) {
            if (cnt < CAP) g_sidx[out + cnt] = j0 + jj;
            cnt++;
        }
    }
    g_scnt[colg * SEG + s] = (cnt < CAP) ? cnt : CAP;
}

__global__ __launch_bounds__(256) void dcalc_kernel()
{
    int colg = blockIdx.x * 256 + threadIdx.x;
    int c = 0;
    #pragma unroll
    for (int s = 0; s < SEG; s++) c += g_scnt[colg * SEG + s];
    g_dvec[colg] = (c > 0) ? rsqrtf((float)c) : 0.0f;
}

// ---------------------------------------------------------------------------
// fp32 -> (hi, lo) bf16 split (activation, layer-1 input)
// ---------------------------------------------------------------------------
__global__ __launch_bounds__(256) void split_kernel(const float* __restrict__ src,
                                                    __nv_bfloat16* __restrict__ hi,
                                                    __nv_bfloat16* __restrict__ lo)
{
    size_t i4 = (size_t)blockIdx.x * 256 + threadIdx.x;
    float4 v = ((const float4*)src)[i4];
    float vv[4] = {v.x, v.y, v.z, v.w};
    ushort h4[4], l4[4];
    #pragma unroll
    for (int k = 0; k < 4; k++) {
        __nv_bfloat16 h = __float2bfloat16(vv[k]);
        __nv_bfloat16 l = __float2bfloat16(vv[k] - __bfloat162float(h));
        h4[k] = __bfloat16_as_ushort(h);
        l4[k] = __bfloat16_as_ushort(l);
    }
    ((ushort4*)hi)[i4] = make_ushort4(h4[0], h4[1], h4[2], h4[3]);
    ((ushort4*)lo)[i4] = make_ushort4(l4[0], l4[1], l4[2], l4[3]);
}

// ---------------------------------------------------------------------------
// Weight transpose + split: W [K,N] fp32 -> W^T [N,K] bf16 hi/lo.
// smem-tiled 64x64, float4 loads, ushort4 stores. blockIdx.z selects weight.
// ---------------------------------------------------------------------------
__global__ __launch_bounds__(256) void wsplit_kernel(const float* __restrict__ Wa,
                                                     const float* __restrict__ Wb,
                                                     __nv_bfloat16* __restrict__ hiT,
                                                     __nv_bfloat16* __restrict__ loT)
{
    __shared__ float s[64][65];
    int z = blockIdx.z;
    const float* W = (z == 0) ? Wa : Wb;
    __nv_bfloat16* ho = hiT + (size_t)z * DD * DD;
    __nv_bfloat16* lo = loT + (size_t)z * DD * DD;

    int tid = threadIdx.x;
    int k0 = blockIdx.y * 64;
    int n0 = blockIdx.x * 64;

    // load 64x64 tile of W (rows = k)
    #pragma unroll
    for (int it = 0; it < 4; it++) {
        int idx = it * 256 + tid;          // 1024 float4
        int r = idx >> 4, cq = idx & 15;   // row, col-quad
        float4 v = *(const float4*)(W + (size_t)(k0 + r) * DD + n0 + cq * 4);
        s[r][cq * 4 + 0] = v.x;
        s[r][cq * 4 + 1] = v.y;
        s[r][cq * 4 + 2] = v.z;
        s[r][cq * 4 + 3] = v.w;
    }
    __syncthreads();

    // store transposed: output row n, cols k (contiguous)
    #pragma unroll
    for (int it = 0; it < 4; it++) {
        int idx = it * 256 + tid;          // 1024 ushort4
        int n = idx >> 4, kq = idx & 15;
        ushort h4[4], l4[4];
        #pragma unroll
        for (int q = 0; q < 4; q++) {
            float v = s[kq * 4 + q][n];
            __nv_bfloat16 h = __float2bfloat16(v);
            __nv_bfloat16 l = __float2bfloat16(v - __bfloat162float(h));
            h4[q] = __bfloat16_as_ushort(h);
            l4[q] = __bfloat16_as_ushort(l);
        }
        size_t o = ((size_t)(n0 + n) * DD + k0 + kq * 4) >> 2;
        ((ushort4*)ho)[o] = make_ushort4(h4[0], h4[1], h4[2], h4[3]);
        ((ushort4*)lo)[o] = make_ushort4(l4[0], l4[1], l4[2], l4[3]);
    }
}

// ---------------------------------------------------------------------------
// mma.sync split-bf16 GEMM: C = Ah*Wh + Ah*Wl + Al*Wh (fp32 accum).
// 8 chunks of K=64; each stages all four operand tiles (64KB) once and runs
// the 3 split passes from smem. Double-buffered cp.async.
// ---------------------------------------------------------------------------
__global__ __launch_bounds__(256, 1) void gemm_mma(
    const __nv_bfloat16* __restrict__ Ah, const __nv_bfloat16* __restrict__ Al,
    const __nv_bfloat16* __restrict__ Wh, const __nv_bfloat16* __restrict__ Wl,
    float* __restrict__ C)
{
    extern __shared__ char smem[];
    uint32_t sbase = smem_u32(smem);
    int tid = threadIdx.x, wid = tid >> 5, lane = tid & 31;
    int bm = blockIdx.x * BM, bn = blockIdx.y * BN;
    int wm = (wid & 3) * 32, wn = (wid >> 2) * 64;

    float acc[2][8][4];
    #pragma unroll
    for (int mf = 0; mf < 2; mf++)
        #pragma unroll
        for (int nf = 0; nf < 8; nf++)
            #pragma unroll
            for (int q = 0; q < 4; q++) acc[mf][nf][q] = 0.0f;

    auto prefetch = [&](int kk) {
        int k0 = kk * BK;
        uint32_t st = sbase + (kk & 1) * STAGE_BYTES;
        #pragma unroll
        for (int i = 0; i < 4; i++) {
            int li = i * 256 + tid;
            int r = li >> 3, c = li & 7;
            size_t src = (size_t)(bm + r) * DD + k0 + c * 8;
            uint32_t sw = r * 128 + ((c ^ (r & 7)) * 16);
            CPASYNC16(st + STG_AH + sw, Ah + src);
            CPASYNC16(st + STG_AL + sw, Al + src);
        }
        #pragma unroll
        for (int i = 0; i < 4; i++) {
            int li = i * 256 + tid;
            int r = li >> 3, c = li & 7;
            size_t src = (size_t)(bn + r) * DD + k0 + c * 8;
            uint32_t sw = r * 128 + ((c ^ (r & 7)) * 16);
            CPASYNC16(st + STG_WH + sw, Wh + src);
            CPASYNC16(st + STG_WL + sw, Wl + src);
        }
        CP_COMMIT();
    };

    prefetch(0);

    for (int kk = 0; kk < NKC; kk++) {
        if (kk + 1 < NKC) {
            prefetch(kk + 1);
            asm volatile("cp.async.wait_group 1;" ::: "memory");
        } else {
            asm volatile("cp.async.wait_group 0;" ::: "memory");
        }
        __syncthreads();

        uint32_t st = sbase + (kk & 1) * STAGE_BYTES;
        #pragma unroll
        for (int pass = 0; pass < 3; pass++) {
            uint32_t ab = st + ((pass == 2) ? STG_AL : STG_AH);
            uint32_t bb2 = st + ((pass == 1) ? STG_WL : STG_WH);
            #pragma unroll
            for (int ks = 0; ks < 4; ks++) {
                uint32_t a[2][4], b[8][2];
                #pragma unroll
                for (int mf = 0; mf < 2; mf++) {
                    int r = wm + mf * 16 + (lane & 15);
                    int c = ks * 2 + (lane >> 4);
                    LDMX4(a[mf], ab + r * 128 + ((c ^ (r & 7)) * 16));
                }
                #pragma unroll
                for (int nq = 0; nq < 4; nq++) {
                    int r = wn + nq * 16 + (lane & 15);
                    int c = ks * 2 + (lane >> 4);
                    uint32_t t[4];
                    LDMX4(t, bb2 + r * 128 + ((c ^ (r & 7)) * 16));
                    b[nq * 2][0]     = t[0];
                    b[nq * 2 + 1][0] = t[1];
                    b[nq * 2][1]     = t[2];
                    b[nq * 2 + 1][1] = t[3];
                }
                #pragma unroll
                for (int mf = 0; mf < 2; mf++)
                    #pragma unroll
                    for (int nf = 0; nf < 8; nf++)
                        MMA16816(acc[mf][nf], a[mf], b[nf]);
            }
        }
        __syncthreads();
    }

    #pragma unroll
    for (int mf = 0; mf < 2; mf++) {
        int r0 = bm + wm + mf * 16 + (lane >> 2);
        #pragma unroll
        for (int nf = 0; nf < 8; nf++) {
            int c0 = bn + wn + nf * 8 + (lane & 3) * 2;
            *(float2*)&C[(size_t)r0 * DD + c0]       = make_float2(acc[mf][nf][0], acc[mf][nf][1]);
            *(float2*)&C[(size_t)(r0 + 8) * DD + c0] = make_float2(acc[mf][nf][2], acc[mf][nf][3]);
        }
    }
}

// ---------------------------------------------------------------------------
// SpMM + bias (+ReLU).  mode 0: relu then split-store hi/lo bf16.
//                       mode 1: plain fp32 store (final layer).
// ---------------------------------------------------------------------------
__global__ __launch_bounds__(128) void spmm_kernel(const float* __restrict__ Z,
                                                   const float* __restrict__ bias,
                                                   float* __restrict__ outf,
                                                   __nv_bfloat16* __restrict__ outh,
                                                   __nv_bfloat16* __restrict__ outl,
                                                   int mode)
{
    int row = blockIdx.x;
    int b   = row >> 12;
    int tid = threadIdx.x;

    __shared__ int   soff[SEG + 1];
    __shared__ int   sj[MAXN];
    __shared__ float sdj[MAXN];

    if (tid == 0) {
        int o = 0;
        #pragma unroll
        for (int s = 0; s < SEG; s++) { soff[s] = o; o += g_scnt[row * SEG + s]; }
        soff[SEG] = o;
    }
    __syncthreads();

    #pragma unroll
    for (int s = 0; s < SEG; s++) {
        int o = soff[s];
        int c = soff[s + 1] - o;
        if (tid < c) {
            int j = g_sidx[((size_t)row * SEG + s) * CAP + tid];
            sj[o + tid]  = j;
            sdj[o + tid] = g_dvec[(b << 12) + j];
        }
    }
    __syncthreads();

    int   total = soff[SEG];
    float di    = g_dvec[row];
    const float4* Zb = (const float4*)(Z + (size_t)b * NN * DD);

    float4 acc = make_float4(0.f, 0.f, 0.f, 0.f);
    int k = 0;
    for (; k + 2 <= total; k += 2) {
        int   j0 = sj[k],  j1 = sj[k + 1];
        float d0 = sdj[k], d1 = sdj[k + 1];
        float4 z0 = Zb[(size_t)j0 * (DD / 4) + tid];
        float4 z1 = Zb[(size_t)j1 * (DD / 4) + tid];
        acc.x = fmaf(d0, z0.x, fmaf(d1, z1.x, acc.x));
        acc.y = fmaf(d0, z0.y, fmaf(d1, z1.y, acc.y));
        acc.z = fmaf(d0, z0.z, fmaf(d1, z1.z, acc.z));
        acc.w = fmaf(d0, z0.w, fmaf(d1, z1.w, acc.w));
    }
    if (k < total) {
        int   j0 = sj[k];
        float d0 = sdj[k];
        float4 z0 = Zb[(size_t)j0 * (DD / 4) + tid];
        acc.x = fmaf(d0, z0.x, acc.x);
        acc.y = fmaf(d0, z0.y, acc.y);
        acc.z = fmaf(d0, z0.z, acc.z);
        acc.w = fmaf(d0, z0.w, acc.w);
    }

    float4 bb = ((const float4*)bias)[tid];
    float v[4];
    v[0] = fmaf(acc.x, di, bb.x);
    v[1] = fmaf(acc.y, di, bb.y);
    v[2] = fmaf(acc.z, di, bb.z);
    v[3] = fmaf(acc.w, di, bb.w);

    if (mode == 0) {
        ushort h4[4], l4[4];
        #pragma unroll
        for (int q = 0; q < 4; q++) {
            float r = fmaxf(v[q], 0.f);
            __nv_bfloat16 h = __float2bfloat16(r);
            __nv_bfloat16 l = __float2bfloat16(r - __bfloat162float(h));
            h4[q] = __bfloat16_as_ushort(h);
            l4[q] = __bfloat16_as_ushort(l);
        }
        ((ushort4*)outh)[(size_t)row * (DD / 4) + tid] = make_ushort4(h4[0], h4[1], h4[2], h4[3]);
        ((ushort4*)outl)[(size_t)row * (DD / 4) + tid] = make_ushort4(l4[0], l4[1], l4[2], l4[3]);
    } else {
        ((float4*)outf)[(size_t)row * (DD / 4) + tid] = make_float4(v[0], v[1], v[2], v[3]);
    }
}

// ---------------------------------------------------------------------------
extern "C" void kernel_launch(void* const* d_in, const int* in_sizes, int n_in,
                              void* d_out, int out_size)
{
    const float* x   = (const float*)d_in[0];
    const float* adj = (const float*)d_in[1];
    const float* W1  = (const float*)d_in[2];
    const float* b1  = (const float*)d_in[3];
    const float* W2  = (const float*)d_in[4];
    const float* b2  = (const float*)d_in[5];
    const float* W3  = (const float*)d_in[6];
    const float* b3  = (const float*)d_in[7];
    float* out = (float*)d_out;

    float *buf0;
    __nv_bfloat16 *hi, *lo, *wh, *wl;
    cudaGetSymbolAddress((void**)&buf0, g_buf0);
    cudaGetSymbolAddress((void**)&hi,   g_hi);
    cudaGetSymbolAddress((void**)&lo,   g_lo);
    cudaGetSymbolAddress((void**)&wh,   g_wh);
    cudaGetSymbolAddress((void**)&wl,   g_wl);

    cudaFuncSetAttribute(gemm_mma, cudaFuncAttributeMaxDynamicSharedMemorySize, GEMM_SMEM);

    // Prep (5 launches so gemm1 lands at ncu skip index 5)
    dim3 wgrid(DD / 64, DD / 64, 2);
    wsplit_kernel<<<wgrid, 256>>>(W1, W2, wh, wl);                      // layers 0,1
    dim3 wgrid2(DD / 64, DD / 64, 1);
    wsplit_kernel<<<wgrid2, 256>>>(W3, W3, wh + 2 * (size_t)DD * DD,
                                   wl + 2 * (size_t)DD * DD);           // layer 2
    dim3 bgrid(NCOL / 256, SEG);
    build_kernel<<<bgrid, 256>>>(adj);
    dcalc_kernel<<<NCOL / 256, 256>>>();
    split_kernel<<<(NCOL * DD / 4) / 256, 256>>>(x, hi, lo);

    dim3 ggrid(NCOL / BM, DD / BN);   // (128, 4)

    // Layer 1
    gemm_mma<<<ggrid, 256, GEMM_SMEM>>>(hi, lo, wh, wl, buf0);
    spmm_kernel<<<NCOL, 128>>>(buf0, b1, nullptr, hi, lo, 0);
    // Layer 2
    gemm_mma<<<ggrid, 256, GEMM_SMEM>>>(hi, lo, wh + (size_t)DD * DD, wl + (size_t)DD * DD, buf0);
    spmm_kernel<<<NCOL, 128>>>(buf0, b2, nullptr, hi, lo, 0);
    // Layer 3 (no relu, fp32 out)
    gemm_mma<<<ggrid, 256, GEMM_SMEM>>>(hi, lo, wh + 2 * (size_t)DD * DD, wl + 2 * (size_t)DD * DD, buf0);
    spmm_kernel<<<NCOL, 128>>>(buf0, b3, out, nullptr, nullptr, 1);
}

// round 5
// speedup vs baseline: 1.1514x; 1.1514x over previous
#include <cuda_runtime.h>
#include <cuda_bf16.h>
#include <cuda_fp16.h>
#include <cstdint>
#include <cstddef>

// Problem constants
#define NB  4
#define NN  4096
#define DD  512
#define NCOL (NB*NN)
#define SEG 16
#define SEGLEN 256
#define CAP 32
#define MAXN (SEG*CAP)

// GEMM tiling (R3 structure: 24 logical K-chunks of 64, double-buffered 32KB)
#define BM 128
#define BN 128
#define BK 64
#define KCHUNKS 24
#define STAGE_BYTES 32768
#define GEMM_SMEM (2*STAGE_BYTES)

__device__ __forceinline__ uint32_t smem_u32(const void* p) {
    uint32_t a;
    asm("{ .reg .u64 t; cvta.to.shared.u64 t, %1; cvt.u32.u64 %0, t; }" : "=r"(a) : "l"(p));
    return a;
}

#define CPASYNC16(s, g) \
    asm volatile("cp.async.cg.shared.global [%0], [%1], 16;" :: "r"(s), "l"(g) : "memory")
#define CP_COMMIT() asm volatile("cp.async.commit_group;" ::: "memory")

#define LDMX4(d, a) \
    asm volatile("ldmatrix.sync.aligned.m8n8.x4.shared.b16 {%0,%1,%2,%3}, [%4];" \
        : "=r"((d)[0]), "=r"((d)[1]), "=r"((d)[2]), "=r"((d)[3]) : "r"(a))

#define MMA16816(c, a, b) \
    asm volatile("mma.sync.aligned.m16n8k16.row.col.f32.bf16.bf16.f32 " \
        "{%0,%1,%2,%3},{%4,%5,%6,%7},{%8,%9},{%0,%1,%2,%3};" \
        : "+f"((c)[0]), "+f"((c)[1]), "+f"((c)[2]), "+f"((c)[3]) \
        : "r"((a)[0]), "r"((a)[1]), "r"((a)[2]), "r"((a)[3]), "r"((b)[0]), "r"((b)[1]))

// ---------------------------------------------------------------------------
// Static scratch
// ---------------------------------------------------------------------------
__device__ int    g_scnt[NCOL*SEG];
__device__ int    g_sidx[(size_t)NCOL*SEG*CAP];
__device__ float  g_dvec[NCOL];
__device__ __half g_z[(size_t)NCOL*DD];             // GEMM output Z (fp16)
__device__ __nv_bfloat16 g_hi[(size_t)NCOL*DD];     // activation hi
__device__ __nv_bfloat16 g_lo[(size_t)NCOL*DD];     // activation lo
__device__ __nv_bfloat16 g_wh[3][(size_t)DD*DD];    // W^T hi
__device__ __nv_bfloat16 g_wl[3][(size_t)DD*DD];    // W^T lo

// ---------------------------------------------------------------------------
// Adjacency sparsify + degrees
// ---------------------------------------------------------------------------
__global__ __launch_bounds__(256) void build_kernel(const float* __restrict__ adj)
{
    int colg = blockIdx.x * 256 + threadIdx.x;
    int s    = blockIdx.y;
    int b    = colg >> 12;
    int i    = colg & (NN - 1);

    const float* base = adj + (size_t)b * NN * NN + i;
    int j0  = s * SEGLEN;
    int cnt = 0;
    int out = (colg * SEG + s) * CAP;

    #pragma unroll 4
    for (int jj = 0; jj < SEGLEN; jj++) {
        float v = __ldg(base + (size_t)(j0 + jj) * NN);
        if (v != 0.0f) {
            if (cnt < CAP) g_sidx[out + cnt] = j0 + jj;
            cnt++;
        }
    }
    g_scnt[colg * SEG + s] = (cnt < CAP) ? cnt : CAP;
}

__global__ __launch_bounds__(256) void dcalc_kernel()
{
    int colg = blockIdx.x * 256 + threadIdx.x;
    int c = 0;
    #pragma unroll
    for (int s = 0; s < SEG; s++) c += g_scnt[colg * SEG + s];
    g_dvec[colg] = (c > 0) ? rsqrtf((float)c) : 0.0f;
}

// ---------------------------------------------------------------------------
// fp32 -> (hi, lo) bf16 split (activation, layer-1 input)
// ---------------------------------------------------------------------------
__global__ __launch_bounds__(256) void split_kernel(const float* __restrict__ src,
                                                    __nv_bfloat16* __restrict__ hi,
                                                    __nv_bfloat16* __restrict__ lo)
{
    size_t i4 = (size_t)blockIdx.x * 256 + threadIdx.x;
    float4 v = ((const float4*)src)[i4];
    float vv[4] = {v.x, v.y, v.z, v.w};
    ushort h4[4], l4[4];
    #pragma unroll
    for (int k = 0; k < 4; k++) {
        __nv_bfloat16 h = __float2bfloat16(vv[k]);
        __nv_bfloat16 l = __float2bfloat16(vv[k] - __bfloat162float(h));
        h4[k] = __bfloat16_as_ushort(h);
        l4[k] = __bfloat16_as_ushort(l);
    }
    ((ushort4*)hi)[i4] = make_ushort4(h4[0], h4[1], h4[2], h4[3]);
    ((ushort4*)lo)[i4] = make_ushort4(l4[0], l4[1], l4[2], l4[3]);
}

// ---------------------------------------------------------------------------
// Weight transpose + split: W [K,N] fp32 -> W^T [N,K] bf16 hi/lo (smem-tiled)
// ---------------------------------------------------------------------------
__global__ __launch_bounds__(256) void wsplit_kernel(const float* __restrict__ Wa,
                                                     const float* __restrict__ Wb,
                                                     __nv_bfloat16* __restrict__ hiT,
                                                     __nv_bfloat16* __restrict__ loT)
{
    __shared__ float s[64][65];
    int z = blockIdx.z;
    const float* W = (z == 0) ? Wa : Wb;
    __nv_bfloat16* ho = hiT + (size_t)z * DD * DD;
    __nv_bfloat16* lo = loT + (size_t)z * DD * DD;

    int tid = threadIdx.x;
    int k0 = blockIdx.y * 64;
    int n0 = blockIdx.x * 64;

    #pragma unroll
    for (int it = 0; it < 4; it++) {
        int idx = it * 256 + tid;
        int r = idx >> 4, cq = idx & 15;
        float4 v = *(const float4*)(W + (size_t)(k0 + r) * DD + n0 + cq * 4);
        s[r][cq * 4 + 0] = v.x;
        s[r][cq * 4 + 1] = v.y;
        s[r][cq * 4 + 2] = v.z;
        s[r][cq * 4 + 3] = v.w;
    }
    __syncthreads();

    #pragma unroll
    for (int it = 0; it < 4; it++) {
        int idx = it * 256 + tid;
        int n = idx >> 4, kq = idx & 15;
        ushort h4[4], l4[4];
        #pragma unroll
        for (int q = 0; q < 4; q++) {
            float v = s[kq * 4 + q][n];
            __nv_bfloat16 h = __float2bfloat16(v);
            __nv_bfloat16 l = __float2bfloat16(v - __bfloat162float(h));
            h4[q] = __bfloat16_as_ushort(h);
            l4[q] = __bfloat16_as_ushort(l);
        }
        size_t o = ((size_t)(n0 + n) * DD + k0 + kq * 4) >> 2;
        ((ushort4*)ho)[o] = make_ushort4(h4[0], h4[1], h4[2], h4[3]);
        ((ushort4*)lo)[o] = make_ushort4(l4[0], l4[1], l4[2], l4[3]);
    }
}

// ---------------------------------------------------------------------------
// mma.sync split-bf16 GEMM (R3 structure): C = Ah*Wh + Ah*Wl + Al*Wh.
// Logical K=1536 over 24 chunks of 64; per-chunk operand pointers select the
// split pass. Output stored as fp16.
// ---------------------------------------------------------------------------
__global__ __launch_bounds__(256, 1) void gemm_mma(
    const __nv_bfloat16* __restrict__ Ah, const __nv_bfloat16* __restrict__ Al,
    const __nv_bfloat16* __restrict__ Wh, const __nv_bfloat16* __restrict__ Wl,
    __half* __restrict__ C)
{
    extern __shared__ char smem[];
    uint32_t sbase = smem_u32(smem);
    int tid = threadIdx.x, wid = tid >> 5, lane = tid & 31;
    int bm = blockIdx.x * BM, bn = blockIdx.y * BN;
    int wm = (wid & 3) * 32, wn = (wid >> 2) * 64;

    float acc[2][8][4];
    #pragma unroll
    for (int mf = 0; mf < 2; mf++)
        #pragma unroll
        for (int nf = 0; nf < 8; nf++)
            #pragma unroll
            for (int q = 0; q < 4; q++) acc[mf][nf][q] = 0.0f;

    auto prefetch = [&](int kk) {
        int p  = kk >> 3;
        int k0 = (kk & 7) * 64;
        const __nv_bfloat16* Ap = (p == 2) ? Al : Ah;
        const __nv_bfloat16* Bp = (p == 1) ? Wl : Wh;
        uint32_t st = sbase + (kk & 1) * STAGE_BYTES;
        #pragma unroll
        for (int i = 0; i < 4; i++) {
            int li = i * 256 + tid;
            int r = li >> 3, c = li & 7;
            uint32_t sa = st + r * 128 + ((c ^ (r & 7)) * 16);
            CPASYNC16(sa, Ap + (size_t)(bm + r) * DD + k0 + c * 8);
        }
        #pragma unroll
        for (int i = 0; i < 4; i++) {
            int li = i * 256 + tid;
            int r = li >> 3, c = li & 7;
            uint32_t sa = st + 16384 + r * 128 + ((c ^ (r & 7)) * 16);
            CPASYNC16(sa, Bp + (size_t)(bn + r) * DD + k0 + c * 8);
        }
        CP_COMMIT();
    };

    prefetch(0);

    for (int kk = 0; kk < KCHUNKS; kk++) {
        if (kk + 1 < KCHUNKS) {
            prefetch(kk + 1);
            asm volatile("cp.async.wait_group 1;" ::: "memory");
        } else {
            asm volatile("cp.async.wait_group 0;" ::: "memory");
        }
        __syncthreads();

        uint32_t st = sbase + (kk & 1) * STAGE_BYTES;
        #pragma unroll
        for (int ks = 0; ks < 4; ks++) {
            uint32_t a[2][4], b[8][2];
            #pragma unroll
            for (int mf = 0; mf < 2; mf++) {
                int r = wm + mf * 16 + (lane & 15);
                int c = ks * 2 + (lane >> 4);
                LDMX4(a[mf], st + r * 128 + ((c ^ (r & 7)) * 16));
            }
            #pragma unroll
            for (int nq = 0; nq < 4; nq++) {
                int r = wn + nq * 16 + (lane & 15);
                int c = ks * 2 + (lane >> 4);
                uint32_t t[4];
                LDMX4(t, st + 16384 + r * 128 + ((c ^ (r & 7)) * 16));
                b[nq * 2][0]     = t[0];
                b[nq * 2 + 1][0] = t[1];
                b[nq * 2][1]     = t[2];
                b[nq * 2 + 1][1] = t[3];
            }
            #pragma unroll
            for (int mf = 0; mf < 2; mf++)
                #pragma unroll
                for (int nf = 0; nf < 8; nf++)
                    MMA16816(acc[mf][nf], a[mf], b[nf]);
        }
        __syncthreads();
    }

    // Epilogue: fp16 stores (half2 per fragment pair)
    #pragma unroll
    for (int mf = 0; mf < 2; mf++) {
        int r0 = bm + wm + mf * 16 + (lane >> 2);
        #pragma unroll
        for (int nf = 0; nf < 8; nf++) {
            int c0 = bn + wn + nf * 8 + (lane & 3) * 2;
            *(__half2*)&C[(size_t)r0 * DD + c0] =
                __floats2half2_rn(acc[mf][nf][0], acc[mf][nf][1]);
            *(__half2*)&C[(size_t)(r0 + 8) * DD + c0] =
                __floats2half2_rn(acc[mf][nf][2], acc[mf][nf][3]);
        }
    }
}

// ---------------------------------------------------------------------------
// SpMM + bias (+ReLU) on fp16 Z.
//   mode 0: relu then split-store hi/lo bf16.  mode 1: fp32 store (final).
// ---------------------------------------------------------------------------
__global__ __launch_bounds__(128) void spmm_kernel(const __half* __restrict__ Z,
                                                   const float* __restrict__ bias,
                                                   float* __restrict__ outf,
                                                   __nv_bfloat16* __restrict__ outh,
                                                   __nv_bfloat16* __restrict__ outl,
                                                   int mode)
{
    int row = blockIdx.x;
    int b   = row >> 12;
    int tid = threadIdx.x;

    __shared__ int   soff[SEG + 1];
    __shared__ int   sj[MAXN];
    __shared__ float sdj[MAXN];

    if (tid == 0) {
        int o = 0;
        #pragma unroll
        for (int s = 0; s < SEG; s++) { soff[s] = o; o += g_scnt[row * SEG + s]; }
        soff[SEG] = o;
    }
    __syncthreads();

    #pragma unroll
    for (int s = 0; s < SEG; s++) {
        int o = soff[s];
        int c = soff[s + 1] - o;
        if (tid < c) {
            int j = g_sidx[((size_t)row * SEG + s) * CAP + tid];
            sj[o + tid]  = j;
            sdj[o + tid] = g_dvec[(b << 12) + j];
        }
    }
    __syncthreads();

    int   total = soff[SEG];
    float di    = g_dvec[row];
    const uint2* Zb = (const uint2*)(Z + (size_t)b * NN * DD);   // 128 uint2 per row

    float4 acc = make_float4(0.f, 0.f, 0.f, 0.f);
    int k = 0;
    for (; k + 2 <= total; k += 2) {
        int   j0 = sj[k],  j1 = sj[k + 1];
        float d0 = sdj[k], d1 = sdj[k + 1];
        uint2 u0 = Zb[(size_t)j0 * 128 + tid];
        uint2 u1 = Zb[(size_t)j1 * 128 + tid];
        float2 a0 = __half22float2(*(__half2*)&u0.x);
        float2 a1 = __half22float2(*(__half2*)&u0.y);
        float2 c0 = __half22float2(*(__half2*)&u1.x);
        float2 c1 = __half22float2(*(__half2*)&u1.y);
        acc.x = fmaf(d0, a0.x, fmaf(d1, c0.x, acc.x));
        acc.y = fmaf(d0, a0.y, fmaf(d1, c0.y, acc.y));
        acc.z = fmaf(d0, a1.x, fmaf(d1, c1.x, acc.z));
        acc.w = fmaf(d0, a1.y, fmaf(d1, c1.y, acc.w));
    }
    if (k < total) {
        int   j0 = sj[k];
        float d0 = sdj[k];
        uint2 u0 = Zb[(size_t)j0 * 128 + tid];
        float2 a0 = __half22float2(*(__half2*)&u0.x);
        float2 a1 = __half22float2(*(__half2*)&u0.y);
        acc.x = fmaf(d0, a0.x, acc.x);
        acc.y = fmaf(d0, a0.y, acc.y);
        acc.z = fmaf(d0, a1.x, acc.z);
        acc.w = fmaf(d0, a1.y, acc.w);
    }

    float4 bb = ((const float4*)bias)[tid];
    float v[4];
    v[0] = fmaf(acc.x, di, bb.x);
    v[1] = fmaf(acc.y, di, bb.y);
    v[2] = fmaf(acc.z, di, bb.z);
    v[3] = fmaf(acc.w, di, bb.w);

    if (mode == 0) {
        ushort h4[4], l4[4];
        #pragma unroll
        for (int q = 0; q < 4; q++) {
            float r = fmaxf(v[q], 0.f);
            __nv_bfloat16 h = __float2bfloat16(r);
            __nv_bfloat16 l = __float2bfloat16(r - __bfloat162float(h));
            h4[q] = __bfloat16_as_ushort(h);
            l4[q] = __bfloat16_as_ushort(l);
        }
        ((ushort4*)outh)[(size_t)row * (DD / 4) + tid] = make_ushort4(h4[0], h4[1], h4[2], h4[3]);
        ((ushort4*)outl)[(size_t)row * (DD / 4) + tid] = make_ushort4(l4[0], l4[1], l4[2], l4[3]);
    } else {
        ((float4*)outf)[(size_t)row * (DD / 4) + tid] = make_float4(v[0], v[1], v[2], v[3]);
    }
}

// ---------------------------------------------------------------------------
extern "C" void kernel_launch(void* const* d_in, const int* in_sizes, int n_in,
                              void* d_out, int out_size)
{
    const float* x   = (const float*)d_in[0];
    const float* adj = (const float*)d_in[1];
    const float* W1  = (const float*)d_in[2];
    const float* b1  = (const float*)d_in[3];
    const float* W2  = (const float*)d_in[4];
    const float* b2  = (const float*)d_in[5];
    const float* W3  = (const float*)d_in[6];
    const float* b3  = (const float*)d_in[7];
    float* out = (float*)d_out;

    __half* zbuf;
    __nv_bfloat16 *hi, *lo, *wh, *wl;
    cudaGetSymbolAddress((void**)&zbuf, g_z);
    cudaGetSymbolAddress((void**)&hi,   g_hi);
    cudaGetSymbolAddress((void**)&lo,   g_lo);
    cudaGetSymbolAddress((void**)&wh,   g_wh);
    cudaGetSymbolAddress((void**)&wl,   g_wl);

    cudaFuncSetAttribute(gemm_mma, cudaFuncAttributeMaxDynamicSharedMemorySize, GEMM_SMEM);

    // Prep
    dim3 wgrid(DD / 64, DD / 64, 2);
    wsplit_kernel<<<wgrid, 256>>>(W1, W2, wh, wl);
    dim3 wgrid2(DD / 64, DD / 64, 1);
    wsplit_kernel<<<wgrid2, 256>>>(W3, W3, wh + 2 * (size_t)DD * DD,
                                   wl + 2 * (size_t)DD * DD);
    dim3 bgrid(NCOL / 256, SEG);
    build_kernel<<<bgrid, 256>>>(adj);
    dcalc_kernel<<<NCOL / 256, 256>>>();
    split_kernel<<<(NCOL * DD / 4) / 256, 256>>>(x, hi, lo);

    dim3 ggrid(NCOL / BM, DD / BN);   // (128, 4)

    // Layer 1
    gemm_mma<<<ggrid, 256, GEMM_SMEM>>>(hi, lo, wh, wl, zbuf);
    spmm_kernel<<<NCOL, 128>>>(zbuf, b1, nullptr, hi, lo, 0);
    // Layer 2
    gemm_mma<<<ggrid, 256, GEMM_SMEM>>>(hi, lo, wh + (size_t)DD * DD, wl + (size_t)DD * DD, zbuf);
    spmm_kernel<<<NCOL, 128>>>(zbuf, b2, nullptr, hi, lo, 0);
    // Layer 3 (no relu, fp32 out)
    gemm_mma<<<ggrid, 256, GEMM_SMEM>>>(hi, lo, wh + 2 * (size_t)DD * DD, wl + 2 * (size_t)DD * DD, zbuf);
    spmm_kernel<<<NCOL, 128>>>(zbuf, b3, out, nullptr, nullptr, 1);
}

// round 8
// speedup vs baseline: 1.5601x; 1.3549x over previous
#include <cuda_runtime.h>
#include <cuda_fp16.h>
#include <cstdint>
#include <cstddef>

// Problem constants
#define NB  4
#define NN  4096
#define DD  512
#define NCOL (NB*NN)
#define SEG 16
#define SEGLEN 256
#define CAP 32
#define MAXN (SEG*CAP)

// GEMM tiling: single-pass fp16, K=512 over 8 chunks of 64, double-buffered
#define BM 128
#define BN 128
#define BK 64
#define NKC 8
#define STAGE_BYTES 32768
#define GEMM_SMEM (2*STAGE_BYTES)

__device__ __forceinline__ uint32_t smem_u32(const void* p) {
    uint32_t a;
    asm("{ .reg .u64 t; cvta.to.shared.u64 t, %1; cvt.u32.u64 %0, t; }" : "=r"(a) : "l"(p));
    return a;
}

#define CPASYNC16(s, g) \
    asm volatile("cp.async.cg.shared.global [%0], [%1], 16;" :: "r"(s), "l"(g) : "memory")
#define CP_COMMIT() asm volatile("cp.async.commit_group;" ::: "memory")

#define LDMX4(d, a) \
    asm volatile("ldmatrix.sync.aligned.m8n8.x4.shared.b16 {%0,%1,%2,%3}, [%4];" \
        : "=r"((d)[0]), "=r"((d)[1]), "=r"((d)[2]), "=r"((d)[3]) : "r"(a))

#define MMA16816F16(c, a, b) \
    asm volatile("mma.sync.aligned.m16n8k16.row.col.f32.f16.f16.f32 " \
        "{%0,%1,%2,%3},{%4,%5,%6,%7},{%8,%9},{%0,%1,%2,%3};" \
        : "+f"((c)[0]), "+f"((c)[1]), "+f"((c)[2]), "+f"((c)[3]) \
        : "r"((a)[0]), "r"((a)[1]), "r"((a)[2]), "r"((a)[3]), "r"((b)[0]), "r"((b)[1]))

// ---------------------------------------------------------------------------
// Static scratch
// ---------------------------------------------------------------------------
__device__ int    g_scnt[NCOL*SEG];
__device__ int    g_sidx[(size_t)NCOL*SEG*CAP];
__device__ float  g_dvec[NCOL];
__device__ __half g_z[(size_t)NCOL*DD];            // GEMM output Z
__device__ __half g_act[(size_t)NCOL*DD];          // activations (fp16)
__device__ __half g_wt[3][(size_t)DD*DD];          // W^T fp16 per layer

// ---------------------------------------------------------------------------
// Adjacency sparsify + degrees
// ---------------------------------------------------------------------------
__global__ __launch_bounds__(256) void build_kernel(const float* __restrict__ adj)
{
    int colg = blockIdx.x * 256 + threadIdx.x;
    int s    = blockIdx.y;
    int b    = colg >> 12;
    int i    = colg & (NN - 1);

    const float* base = adj + (size_t)b * NN * NN + i;
    int j0  = s * SEGLEN;
    int cnt = 0;
    int out = (colg * SEG + s) * CAP;

    #pragma unroll 4
    for (int jj = 0; jj < SEGLEN; jj++) {
        float v = __ldg(base + (size_t)(j0 + jj) * NN);
        if (v != 0.0f) {
            if (cnt < CAP) g_sidx[out + cnt] = j0 + jj;
            cnt++;
        }
    }
    g_scnt[colg * SEG + s] = (cnt < CAP) ? cnt : CAP;
}

__global__ __launch_bounds__(256) void dcalc_kernel()
{
    int colg = blockIdx.x * 256 + threadIdx.x;
    int c = 0;
    #pragma unroll
    for (int s = 0; s < SEG; s++) c += g_scnt[colg * SEG + s];
    g_dvec[colg] = (c > 0) ? rsqrtf((float)c) : 0.0f;
}

// ---------------------------------------------------------------------------
// fp32 -> fp16 convert (layer-1 activations)
// ---------------------------------------------------------------------------
__global__ __launch_bounds__(256) void convert_kernel(const float* __restrict__ src,
                                                      __half* __restrict__ dst)
{
    size_t i4 = (size_t)blockIdx.x * 256 + threadIdx.x;
    float4 v = ((const float4*)src)[i4];
    __half2 h0 = __floats2half2_rn(v.x, v.y);
    __half2 h1 = __floats2half2_rn(v.z, v.w);
    uint2 u;
    u.x = *(uint32_t*)&h0;
    u.y = *(uint32_t*)&h1;
    ((uint2*)dst)[i4] = u;
}

// ---------------------------------------------------------------------------
// Weight transpose: W [K,N] fp32 -> W^T [N,K] fp16 (smem-tiled)
// ---------------------------------------------------------------------------
__global__ __launch_bounds__(256) void wt_kernel(const float* __restrict__ Wa,
                                                 const float* __restrict__ Wb,
                                                 const float* __restrict__ Wc,
                                                 __half* __restrict__ outT)
{
    __shared__ float s[64][65];
    int z = blockIdx.z;
    const float* W = (z == 0) ? Wa : ((z == 1) ? Wb : Wc);
    __half* ho = outT + (size_t)z * DD * DD;

    int tid = threadIdx.x;
    int k0 = blockIdx.y * 64;
    int n0 = blockIdx.x * 64;

    #pragma unroll
    for (int it = 0; it < 4; it++) {
        int idx = it * 256 + tid;
        int r = idx >> 4, cq = idx & 15;
        float4 v = *(const float4*)(W + (size_t)(k0 + r) * DD + n0 + cq * 4);
        s[r][cq * 4 + 0] = v.x;
        s[r][cq * 4 + 1] = v.y;
        s[r][cq * 4 + 2] = v.z;
        s[r][cq * 4 + 3] = v.w;
    }
    __syncthreads();

    #pragma unroll
    for (int it = 0; it < 4; it++) {
        int idx = it * 256 + tid;
        int n = idx >> 4, kq = idx & 15;
        __half2 h0 = __floats2half2_rn(s[kq * 4 + 0][n], s[kq * 4 + 1][n]);
        __half2 h1 = __floats2half2_rn(s[kq * 4 + 2][n], s[kq * 4 + 3][n]);
        uint2 u;
        u.x = *(uint32_t*)&h0;
        u.y = *(uint32_t*)&h1;
        ((uint2*)ho)[((size_t)(n0 + n) * DD + k0 + kq * 4) >> 2] = u;
    }
}

// ---------------------------------------------------------------------------
// Single-pass fp16 GEMM: C[M,512] = A[M,512] @ W^T (fp32 accum, fp16 out).
// 128x128 CTA tile, 8 warps of 32x64, double-buffered cp.async, swizzled.
// ---------------------------------------------------------------------------
__global__ __launch_bounds__(256, 1) void gemm_mma(
    const __half* __restrict__ A, const __half* __restrict__ WT,
    __half* __restrict__ C)
{
    extern __shared__ char smem[];
    uint32_t sbase = smem_u32(smem);
    int tid = threadIdx.x, wid = tid >> 5, lane = tid & 31;
    int bm = blockIdx.x * BM, bn = blockIdx.y * BN;
    int wm = (wid & 3) * 32, wn = (wid >> 2) * 64;

    float acc[2][8][4];
    #pragma unroll
    for (int mf = 0; mf < 2; mf++)
        #pragma unroll
        for (int nf = 0; nf < 8; nf++)
            #pragma unroll
            for (int q = 0; q < 4; q++) acc[mf][nf][q] = 0.0f;

    auto prefetch = [&](int kk) {
        int k0 = kk * BK;
        uint32_t st = sbase + (kk & 1) * STAGE_BYTES;
        #pragma unroll
        for (int i = 0; i < 4; i++) {
            int li = i * 256 + tid;
            int r = li >> 3, c = li & 7;
            uint32_t sa = st + r * 128 + ((c ^ (r & 7)) * 16);
            CPASYNC16(sa, A + (size_t)(bm + r) * DD + k0 + c * 8);
        }
        #pragma unroll
        for (int i = 0; i < 4; i++) {
            int li = i * 256 + tid;
            int r = li >> 3, c = li & 7;
            uint32_t sa = st + 16384 + r * 128 + ((c ^ (r & 7)) * 16);
            CPASYNC16(sa, WT + (size_t)(bn + r) * DD + k0 + c * 8);
        }
        CP_COMMIT();
    };

    prefetch(0);

    for (int kk = 0; kk < NKC; kk++) {
        if (kk + 1 < NKC) {
            prefetch(kk + 1);
            asm volatile("cp.async.wait_group 1;" ::: "memory");
        } else {
            asm volatile("cp.async.wait_group 0;" ::: "memory");
        }
        __syncthreads();

        uint32_t st = sbase + (kk & 1) * STAGE_BYTES;
        #pragma unroll
        for (int ks = 0; ks < 4; ks++) {
            uint32_t a[2][4], b[8][2];
            #pragma unroll
            for (int mf = 0; mf < 2; mf++) {
                int r = wm + mf * 16 + (lane & 15);
                int c = ks * 2 + (lane >> 4);
                LDMX4(a[mf], st + r * 128 + ((c ^ (r & 7)) * 16));
            }
            #pragma unroll
            for (int nq = 0; nq < 4; nq++) {
                int r = wn + nq * 16 + (lane & 15);
                int c = ks * 2 + (lane >> 4);
                uint32_t t[4];
                LDMX4(t, st + 16384 + r * 128 + ((c ^ (r & 7)) * 16));
                b[nq * 2][0]     = t[0];
                b[nq * 2 + 1][0] = t[1];
                b[nq * 2][1]     = t[2];
                b[nq * 2 + 1][1] = t[3];
            }
            #pragma unroll
            for (int mf = 0; mf < 2; mf++)
                #pragma unroll
                for (int nf = 0; nf < 8; nf++)
                    MMA16816F16(acc[mf][nf], a[mf], b[nf]);
        }
        __syncthreads();
    }

    // Epilogue: fp16 stores
    #pragma unroll
    for (int mf = 0; mf < 2; mf++) {
        int r0 = bm + wm + mf * 16 + (lane >> 2);
        #pragma unroll
        for (int nf = 0; nf < 8; nf++) {
            int c0 = bn + wn + nf * 8 + (lane & 3) * 2;
            *(__half2*)&C[(size_t)r0 * DD + c0] =
                __floats2half2_rn(acc[mf][nf][0], acc[mf][nf][1]);
            *(__half2*)&C[(size_t)(r0 + 8) * DD + c0] =
                __floats2half2_rn(acc[mf][nf][2], acc[mf][nf][3]);
        }
    }
}

// ---------------------------------------------------------------------------
// SpMM + bias (+ReLU) on fp16 Z.
//   mode 0: relu, fp16 store to act buffer.   mode 1: fp32 store (final).
// Gather loop unrolled x4 for MLP.
// ---------------------------------------------------------------------------
__global__ __launch_bounds__(128) void spmm_kernel(const __half* __restrict__ Z,
                                                   const float* __restrict__ bias,
                                                   float* __restrict__ outf,
                                                   __half* __restrict__ outh,
                                                   int mode)
{
    int row = blockIdx.x;
    int b   = row >> 12;
    int tid = threadIdx.x;

    __shared__ int   soff[SEG + 1];
    __shared__ int   sj[MAXN];
    __shared__ float sdj[MAXN];

    if (tid == 0) {
        int o = 0;
        #pragma unroll
        for (int s = 0; s < SEG; s++) { soff[s] = o; o += g_scnt[row * SEG + s]; }
        soff[SEG] = o;
    }
    __syncthreads();

    #pragma unroll
    for (int s = 0; s < SEG; s++) {
        int o = soff[s];
        int c = soff[s + 1] - o;
        if (tid < c) {
            int j = g_sidx[((size_t)row * SEG + s) * CAP + tid];
            sj[o + tid]  = j;
            sdj[o + tid] = g_dvec[(b << 12) + j];
        }
    }
    __syncthreads();

    int   total = soff[SEG];
    float di    = g_dvec[row];
    const uint2* Zb = (const uint2*)(Z + (size_t)b * NN * DD);   // 128 uint2/row

    float4 acc = make_float4(0.f, 0.f, 0.f, 0.f);
    int k = 0;
    for (; k + 4 <= total; k += 4) {
        uint2 u0 = Zb[(size_t)sj[k]     * 128 + tid];
        uint2 u1 = Zb[(size_t)sj[k + 1] * 128 + tid];
        uint2 u2 = Zb[(size_t)sj[k + 2] * 128 + tid];
        uint2 u3 = Zb[(size_t)sj[k + 3] * 128 + tid];
        float d0 = sdj[k], d1 = sdj[k + 1], d2 = sdj[k + 2], d3 = sdj[k + 3];
        float2 p, q;
        p = __half22float2(*(__half2*)&u0.x); q = __half22float2(*(__half2*)&u0.y);
        acc.x = fmaf(d0, p.x, acc.x); acc.y = fmaf(d0, p.y, acc.y);
        acc.z = fmaf(d0, q.x, acc.z); acc.w = fmaf(d0, q.y, acc.w);
        p = __half22float2(*(__half2*)&u1.x); q = __half22float2(*(__half2*)&u1.y);
        acc.x = fmaf(d1, p.x, acc.x); acc.y = fmaf(d1, p.y, acc.y);
        acc.z = fmaf(d1, q.x, acc.z); acc.w = fmaf(d1, q.y, acc.w);
        p = __half22float2(*(__half2*)&u2.x); q = __half22float2(*(__half2*)&u2.y);
        acc.x = fmaf(d2, p.x, acc.x); acc.y = fmaf(d2, p.y, acc.y);
        acc.z = fmaf(d2, q.x, acc.z); acc.w = fmaf(d2, q.y, acc.w);
        p = __half22float2(*(__half2*)&u3.x); q = __half22float2(*(__half2*)&u3.y);
        acc.x = fmaf(d3, p.x, acc.x); acc.y = fmaf(d3, p.y, acc.y);
        acc.z = fmaf(d3, q.x, acc.z); acc.w = fmaf(d3, q.y, acc.w);
    }
    for (; k < total; k++) {
        uint2 u0 = Zb[(size_t)sj[k] * 128 + tid];
        float d0 = sdj[k];
        float2 p = __half22float2(*(__half2*)&u0.x);
        float2 q = __half22float2(*(__half2*)&u0.y);
        acc.x = fmaf(d0, p.x, acc.x); acc.y = fmaf(d0, p.y, acc.y);
        acc.z = fmaf(d0, q.x, acc.z); acc.w = fmaf(d0, q.y, acc.w);
    }

    float4 bb = ((const float4*)bias)[tid];
    float v0 = fmaf(acc.x, di, bb.x);
    float v1 = fmaf(acc.y, di, bb.y);
    float v2 = fmaf(acc.z, di, bb.z);
    float v3 = fmaf(acc.w, di, bb.w);

    if (mode == 0) {
        v0 = fmaxf(v0, 0.f); v1 = fmaxf(v1, 0.f);
        v2 = fmaxf(v2, 0.f); v3 = fmaxf(v3, 0.f);
        __half2 h0 = __floats2half2_rn(v0, v1);
        __half2 h1 = __floats2half2_rn(v2, v3);
        uint2 u;
        u.x = *(uint32_t*)&h0;
        u.y = *(uint32_t*)&h1;
        ((uint2*)outh)[(size_t)row * 128 + tid] = u;
    } else {
        ((float4*)outf)[(size_t)row * 128 + tid] = make_float4(v0, v1, v2, v3);
    }
}

// ---------------------------------------------------------------------------
extern "C" void kernel_launch(void* const* d_in, const int* in_sizes, int n_in,
                              void* d_out, int out_size)
{
    const float* x   = (const float*)d_in[0];
    const float* adj = (const float*)d_in[1];
    const float* W1  = (const float*)d_in[2];
    const float* b1  = (const float*)d_in[3];
    const float* W2  = (const float*)d_in[4];
    const float* b2  = (const float*)d_in[5];
    const float* W3  = (const float*)d_in[6];
    const float* b3  = (const float*)d_in[7];
    float* out = (float*)d_out;

    __half *zbuf, *act, *wt;
    cudaGetSymbolAddress((void**)&zbuf, g_z);
    cudaGetSymbolAddress((void**)&act,  g_act);
    cudaGetSymbolAddress((void**)&wt,   g_wt);

    cudaFuncSetAttribute(gemm_mma, cudaFuncAttributeMaxDynamicSharedMemorySize, GEMM_SMEM);

    // Prep
    dim3 wgrid(DD / 64, DD / 64, 3);
    wt_kernel<<<wgrid, 256>>>(W1, W2, W3, wt);
    dim3 bgrid(NCOL / 256, SEG);
    build_kernel<<<bgrid, 256>>>(adj);
    dcalc_kernel<<<NCOL / 256, 256>>>();
    convert_kernel<<<(NCOL * DD / 4) / 256, 256>>>(x, act);

    dim3 ggrid(NCOL / BM, DD / BN);   // (128, 4)

    // Layer 1
    gemm_mma<<<ggrid, 256, GEMM_SMEM>>>(act, wt, zbuf);
    spmm_kernel<<<NCOL, 128>>>(zbuf, b1, nullptr, act, 0);
    // Layer 2
    gemm_mma<<<ggrid, 256, GEMM_SMEM>>>(act, wt + (size_t)DD * DD, zbuf);
    spmm_kernel<<<NCOL, 128>>>(zbuf, b2, nullptr, act, 0);
    // Layer 3 (no relu, fp32 out)
    gemm_mma<<<ggrid, 256, GEMM_SMEM>>>(act, wt + 2 * (size_t)DD * DD, zbuf);
    spmm_kernel<<<NCOL, 128>>>(zbuf, b3, out, nullptr, 1);
}

// round 11
// speedup vs baseline: 1.6226x; 1.0400x over previous
#include <cuda_runtime.h>
#include <cuda_fp16.h>
#include <cstdint>
#include <cstddef>

// Problem constants
#define NB  4
#define NN  4096
#define DD  512
#define NCOL (NB*NN)
#define SEG 16
#define SEGLEN 256
#define CAP 32
#define MAXN (SEG*CAP)

// GEMM tiling: single-pass fp16, K=512 over 8 chunks of 64, double-buffered
#define BM 128
#define BN 128
#define BK 64
#define NKC 8
#define STAGE_BYTES 32768
#define GEMM_SMEM (2*STAGE_BYTES)

__device__ __forceinline__ uint32_t smem_u32(const void* p) {
    uint32_t a;
    asm("{ .reg .u64 t; cvta.to.shared.u64 t, %1; cvt.u32.u64 %0, t; }" : "=r"(a) : "l"(p));
    return a;
}

#define CPASYNC16(s, g) \
    asm volatile("cp.async.cg.shared.global [%0], [%1], 16;" :: "r"(s), "l"(g) : "memory")
#define CP_COMMIT() asm volatile("cp.async.commit_group;" ::: "memory")

#define LDMX4(d, a) \
    asm volatile("ldmatrix.sync.aligned.m8n8.x4.shared.b16 {%0,%1,%2,%3}, [%4];" \
        : "=r"((d)[0]), "=r"((d)[1]), "=r"((d)[2]), "=r"((d)[3]) : "r"(a))

#define MMA16816F16(c, a, b) \
    asm volatile("mma.sync.aligned.m16n8k16.row.col.f32.f16.f16.f32 " \
        "{%0,%1,%2,%3},{%4,%5,%6,%7},{%8,%9},{%0,%1,%2,%3};" \
        : "+f"((c)[0]), "+f"((c)[1]), "+f"((c)[2]), "+f"((c)[3]) \
        : "r"((a)[0]), "r"((a)[1]), "r"((a)[2]), "r"((a)[3]), "r"((b)[0]), "r"((b)[1]))

// ---------------------------------------------------------------------------
// Static scratch
// ---------------------------------------------------------------------------
__device__ int    g_scnt[NCOL*SEG];
__device__ int    g_sidx[(size_t)NCOL*SEG*CAP];
__device__ float  g_dvec[NCOL];
__device__ __half g_z[(size_t)NCOL*DD];            // GEMM output Z
__device__ __half g_act[(size_t)NCOL*DD];          // activations (fp16)
__device__ __half g_wt[3][(size_t)DD*DD];          // W^T fp16 per layer

// ---------------------------------------------------------------------------
// Adjacency sparsify + degrees
// ---------------------------------------------------------------------------
__global__ __launch_bounds__(256) void build_kernel(const float* __restrict__ adj)
{
    int colg = blockIdx.x * 256 + threadIdx.x;
    int s    = blockIdx.y;
    int b    = colg >> 12;
    int i    = colg & (NN - 1);

    const float* base = adj + (size_t)b * NN * NN + i;
    int j0  = s * SEGLEN;
    int cnt = 0;
    int out = (colg * SEG + s) * CAP;

    #pragma unroll 4
    for (int jj = 0; jj < SEGLEN; jj++) {
        float v = __ldg(base + (size_t)(j0 + jj) * NN);
        if (v != 0.0f) {
            if (cnt < CAP) g_sidx[out + cnt] = j0 + jj;
            cnt++;
        }
    }
    g_scnt[colg * SEG + s] = (cnt < CAP) ? cnt : CAP;
}

__global__ __launch_bounds__(256) void dcalc_kernel()
{
    int colg = blockIdx.x * 256 + threadIdx.x;
    int c = 0;
    #pragma unroll
    for (int s = 0; s < SEG; s++) c += g_scnt[colg * SEG + s];
    g_dvec[colg] = (c > 0) ? rsqrtf((float)c) : 0.0f;
}

// ---------------------------------------------------------------------------
// fp32 -> fp16 convert (layer-1 activations)
// ---------------------------------------------------------------------------
__global__ __launch_bounds__(256) void convert_kernel(const float* __restrict__ src,
                                                      __half* __restrict__ dst)
{
    size_t i4 = (size_t)blockIdx.x * 256 + threadIdx.x;
    float4 v = ((const float4*)src)[i4];
    __half2 h0 = __floats2half2_rn(v.x, v.y);
    __half2 h1 = __floats2half2_rn(v.z, v.w);
    uint2 u;
    u.x = *(uint32_t*)&h0;
    u.y = *(uint32_t*)&h1;
    ((uint2*)dst)[i4] = u;
}

// ---------------------------------------------------------------------------
// Weight transpose: W [K,N] fp32 -> W^T [N,K] fp16 (smem-tiled)
// ---------------------------------------------------------------------------
__global__ __launch_bounds__(256) void wt_kernel(const float* __restrict__ Wa,
                                                 const float* __restrict__ Wb,
                                                 const float* __restrict__ Wc,
                                                 __half* __restrict__ outT)
{
    __shared__ float s[64][65];
    int z = blockIdx.z;
    const float* W = (z == 0) ? Wa : ((z == 1) ? Wb : Wc);
    __half* ho = outT + (size_t)z * DD * DD;

    int tid = threadIdx.x;
    int k0 = blockIdx.y * 64;
    int n0 = blockIdx.x * 64;

    #pragma unroll
    for (int it = 0; it < 4; it++) {
        int idx = it * 256 + tid;
        int r = idx >> 4, cq = idx & 15;
        float4 v = *(const float4*)(W + (size_t)(k0 + r) * DD + n0 + cq * 4);
        s[r][cq * 4 + 0] = v.x;
        s[r][cq * 4 + 1] = v.y;
        s[r][cq * 4 + 2] = v.z;
        s[r][cq * 4 + 3] = v.w;
    }
    __syncthreads();

    #pragma unroll
    for (int it = 0; it < 4; it++) {
        int idx = it * 256 + tid;
        int n = idx >> 4, kq = idx & 15;
        __half2 h0 = __floats2half2_rn(s[kq * 4 + 0][n], s[kq * 4 + 1][n]);
        __half2 h1 = __floats2half2_rn(s[kq * 4 + 2][n], s[kq * 4 + 3][n]);
        uint2 u;
        u.x = *(uint32_t*)&h0;
        u.y = *(uint32_t*)&h1;
        ((uint2*)ho)[((size_t)(n0 + n) * DD + k0 + kq * 4) >> 2] = u;
    }
}

// ---------------------------------------------------------------------------
// Single-pass fp16 GEMM: C[M,512] = A[M,512] @ W^T (fp32 accum, fp16 out).
// ---------------------------------------------------------------------------
__global__ __launch_bounds__(256, 1) void gemm_mma(
    const __half* __restrict__ A, const __half* __restrict__ WT,
    __half* __restrict__ C)
{
    extern __shared__ char smem[];
    uint32_t sbase = smem_u32(smem);
    int tid = threadIdx.x, wid = tid >> 5, lane = tid & 31;
    int bm = blockIdx.x * BM, bn = blockIdx.y * BN;
    int wm = (wid & 3) * 32, wn = (wid >> 2) * 64;

    float acc[2][8][4];
    #pragma unroll
    for (int mf = 0; mf < 2; mf++)
        #pragma unroll
        for (int nf = 0; nf < 8; nf++)
            #pragma unroll
            for (int q = 0; q < 4; q++) acc[mf][nf][q] = 0.0f;

    auto prefetch = [&](int kk) {
        int k0 = kk * BK;
        uint32_t st = sbase + (kk & 1) * STAGE_BYTES;
        #pragma unroll
        for (int i = 0; i < 4; i++) {
            int li = i * 256 + tid;
            int r = li >> 3, c = li & 7;
            uint32_t sa = st + r * 128 + ((c ^ (r & 7)) * 16);
            CPASYNC16(sa, A + (size_t)(bm + r) * DD + k0 + c * 8);
        }
        #pragma unroll
        for (int i = 0; i < 4; i++) {
            int li = i * 256 + tid;
            int r = li >> 3, c = li & 7;
            uint32_t sa = st + 16384 + r * 128 + ((c ^ (r & 7)) * 16);
            CPASYNC16(sa, WT + (size_t)(bn + r) * DD + k0 + c * 8);
        }
        CP_COMMIT();
    };

    prefetch(0);

    for (int kk = 0; kk < NKC; kk++) {
        if (kk + 1 < NKC) {
            prefetch(kk + 1);
            asm volatile("cp.async.wait_group 1;" ::: "memory");
        } else {
            asm volatile("cp.async.wait_group 0;" ::: "memory");
        }
        __syncthreads();

        uint32_t st = sbase + (kk & 1) * STAGE_BYTES;
        #pragma unroll
        for (int ks = 0; ks < 4; ks++) {
            uint32_t a[2][4], b[8][2];
            #pragma unroll
            for (int mf = 0; mf < 2; mf++) {
                int r = wm + mf * 16 + (lane & 15);
                int c = ks * 2 + (lane >> 4);
                LDMX4(a[mf], st + r * 128 + ((c ^ (r & 7)) * 16));
            }
            #pragma unroll
            for (int nq = 0; nq < 4; nq++) {
                int r = wn + nq * 16 + (lane & 15);
                int c = ks * 2 + (lane >> 4);
                uint32_t t[4];
                LDMX4(t, st + 16384 + r * 128 + ((c ^ (r & 7)) * 16));
                b[nq * 2][0]     = t[0];
                b[nq * 2 + 1][0] = t[1];
                b[nq * 2][1]     = t[2];
                b[nq * 2 + 1][1] = t[3];
            }
            #pragma unroll
            for (int mf = 0; mf < 2; mf++)
                #pragma unroll
                for (int nf = 0; nf < 8; nf++)
                    MMA16816F16(acc[mf][nf], a[mf], b[nf]);
        }
        __syncthreads();
    }

    #pragma unroll
    for (int mf = 0; mf < 2; mf++) {
        int r0 = bm + wm + mf * 16 + (lane >> 2);
        #pragma unroll
        for (int nf = 0; nf < 8; nf++) {
            int c0 = bn + wn + nf * 8 + (lane & 3) * 2;
            *(__half2*)&C[(size_t)r0 * DD + c0] =
                __floats2half2_rn(acc[mf][nf][0], acc[mf][nf][1]);
            *(__half2*)&C[(size_t)(r0 + 8) * DD + c0] =
                __floats2half2_rn(acc[mf][nf][2], acc[mf][nf][3]);
        }
    }
}

// ---------------------------------------------------------------------------
// SpMM + bias (+ReLU) on fp16 Z. Gather unrolled x8 with hoisted indices.
//   mode 0: relu, fp16 store.   mode 1: fp32 store (final).
// ---------------------------------------------------------------------------
__global__ __launch_bounds__(128) void spmm_kernel(const __half* __restrict__ Z,
                                                   const float* __restrict__ bias,
                                                   float* __restrict__ outf,
                                                   __half* __restrict__ outh,
                                                   int mode)
{
    int row = blockIdx.x;
    int b   = row >> 12;
    int tid = threadIdx.x;

    __shared__ int   soff[SEG + 1];
    __shared__ int   sj[MAXN];
    __shared__ float sdj[MAXN];

    if (tid == 0) {
        int o = 0;
        #pragma unroll
        for (int s = 0; s < SEG; s++) { soff[s] = o; o += g_scnt[row * SEG + s]; }
        soff[SEG] = o;
    }
    __syncthreads();

    #pragma unroll
    for (int s = 0; s < SEG; s++) {
        int o = soff[s];
        int c = soff[s + 1] - o;
        if (tid < c) {
            int j = g_sidx[((size_t)row * SEG + s) * CAP + tid];
            sj[o + tid]  = j;
            sdj[o + tid] = g_dvec[(b << 12) + j];
        }
    }
    __syncthreads();

    int   total = soff[SEG];
    float di    = g_dvec[row];
    const uint2* Zb = (const uint2*)(Z + (size_t)b * NN * DD) + tid;  // row stride 128

    float4 acc = make_float4(0.f, 0.f, 0.f, 0.f);
    int k = 0;
    for (; k + 8 <= total; k += 8) {
        // hoist indices + weights, then batch 8 independent gathers
        int   jr[8];
        float dr[8];
        #pragma unroll
        for (int q = 0; q < 8; q++) { jr[q] = sj[k + q]; dr[q] = sdj[k + q]; }
        uint2 u[8];
        #pragma unroll
        for (int q = 0; q < 8; q++) u[q] = Zb[(size_t)jr[q] * 128];
        #pragma unroll
        for (int q = 0; q < 8; q++) {
            float2 p = __half22float2(*(__half2*)&u[q].x);
            float2 r = __half22float2(*(__half2*)&u[q].y);
            acc.x = fmaf(dr[q], p.x, acc.x); acc.y = fmaf(dr[q], p.y, acc.y);
            acc.z = fmaf(dr[q], r.x, acc.z); acc.w = fmaf(dr[q], r.y, acc.w);
        }
    }
    if (k + 4 <= total) {
        int   jr[4];
        float dr[4];
        #pragma unroll
        for (int q = 0; q < 4; q++) { jr[q] = sj[k + q]; dr[q] = sdj[k + q]; }
        uint2 u[4];
        #pragma unroll
        for (int q = 0; q < 4; q++) u[q] = Zb[(size_t)jr[q] * 128];
        #pragma unroll
        for (int q = 0; q < 4; q++) {
            float2 p = __half22float2(*(__half2*)&u[q].x);
            float2 r = __half22float2(*(__half2*)&u[q].y);
            acc.x = fmaf(dr[q], p.x, acc.x); acc.y = fmaf(dr[q], p.y, acc.y);
            acc.z = fmaf(dr[q], r.x, acc.z); acc.w = fmaf(dr[q], r.y, acc.w);
        }
        k += 4;
    }
    for (; k < total; k++) {
        uint2 u0 = Zb[(size_t)sj[k] * 128];
        float d0 = sdj[k];
        float2 p = __half22float2(*(__half2*)&u0.x);
        float2 r = __half22float2(*(__half2*)&u0.y);
        acc.x = fmaf(d0, p.x, acc.x); acc.y = fmaf(d0, p.y, acc.y);
        acc.z = fmaf(d0, r.x, acc.z); acc.w = fmaf(d0, r.y, acc.w);
    }

    float4 bb = ((const float4*)bias)[tid];
    float v0 = fmaf(acc.x, di, bb.x);
    float v1 = fmaf(acc.y, di, bb.y);
    float v2 = fmaf(acc.z, di, bb.z);
    float v3 = fmaf(acc.w, di, bb.w);

    if (mode == 0) {
        v0 = fmaxf(v0, 0.f); v1 = fmaxf(v1, 0.f);
        v2 = fmaxf(v2, 0.f); v3 = fmaxf(v3, 0.f);
        __half2 h0 = __floats2half2_rn(v0, v1);
        __half2 h1 = __floats2half2_rn(v2, v3);
        uint2 u;
        u.x = *(uint32_t*)&h0;
        u.y = *(uint32_t*)&h1;
        ((uint2*)outh)[(size_t)row * 128 + tid] = u;
    } else {
        ((float4*)outf)[(size_t)row * 128 + tid] = make_float4(v0, v1, v2, v3);
    }
}

// ---------------------------------------------------------------------------
extern "C" void kernel_launch(void* const* d_in, const int* in_sizes, int n_in,
                              void* d_out, int out_size)
{
    const float* x   = (const float*)d_in[0];
    const float* adj = (const float*)d_in[1];
    const float* W1  = (const float*)d_in[2];
    const float* b1  = (const float*)d_in[3];
    const float* W2  = (const float*)d_in[4];
    const float* b2  = (const float*)d_in[5];
    const float* W3  = (const float*)d_in[6];
    const float* b3  = (const float*)d_in[7];
    float* out = (float*)d_out;

    __half *zbuf, *act, *wt;
    cudaGetSymbolAddress((void**)&zbuf, g_z);
    cudaGetSymbolAddress((void**)&act,  g_act);
    cudaGetSymbolAddress((void**)&wt,   g_wt);

    cudaFuncSetAttribute(gemm_mma, cudaFuncAttributeMaxDynamicSharedMemorySize, GEMM_SMEM);

    // Prep
    dim3 wgrid(DD / 64, DD / 64, 3);
    wt_kernel<<<wgrid, 256>>>(W1, W2, W3, wt);
    dim3 bgrid(NCOL / 256, SEG);
    build_kernel<<<bgrid, 256>>>(adj);
    dcalc_kernel<<<NCOL / 256, 256>>>();
    convert_kernel<<<(NCOL * DD / 4) / 256, 256>>>(x, act);

    dim3 ggrid(NCOL / BM, DD / BN);   // (128, 4)

    // Layer 1
    gemm_mma<<<ggrid, 256, GEMM_SMEM>>>(act, wt, zbuf);
    spmm_kernel<<<NCOL, 128>>>(zbuf, b1, nullptr, act, 0);
    // Layer 2
    gemm_mma<<<ggrid, 256, GEMM_SMEM>>>(act, wt + (size_t)DD * DD, zbuf);
    spmm_kernel<<<NCOL, 128>>>(zbuf, b2, nullptr, act, 0);
    // Layer 3 (no relu, fp32 out)
    gemm_mma<<<ggrid, 256, GEMM_SMEM>>>(act, wt + 2 * (size_t)DD * DD, zbuf);
    spmm_kernel<<<NCOL, 128>>>(zbuf, b3, out, nullptr, 1);
}